// round 10
// baseline (speedup 1.0000x reference)
#include <cuda_runtime.h>
#include <cuda_bf16.h>

#define N_NODES 100000
#define N_EDGES 1600000

// scratch (allocation-free rule: __device__ globals). float4-typed => 16B aligned.
__device__ float4 g_bufA[N_NODES * 32];   // 128 floats per node
__device__ float4 g_bufB[N_NODES * 32];
__device__ float  g_deg_out[N_NODES];
__device__ float  g_deg_in[N_NODES];
__device__ int    g_src[N_EDGES];         // decoded int32 indices
__device__ int    g_dst[N_EDGES];
__device__ int    g_is64;

// ---------------- index dtype probe + decode ----------------
// int64 little-endian storage with values < 2^31 => every odd 32-bit word is 0.
__global__ void k_probe(const int* __restrict__ raw_src, const int* __restrict__ raw_dst) {
    __shared__ int any;
    if (threadIdx.x == 0) any = 0;
    __syncthreads();
    int t = threadIdx.x;
    int acc = 0;
    for (int i = 0; i < 4; i++) {
        int w = 2 * (t + i * 256) + 1;
        acc |= raw_src[w] | raw_dst[w];
    }
    if (acc) atomicOr(&any, 1);
    __syncthreads();
    if (threadIdx.x == 0) g_is64 = (any == 0);
}
__global__ void k_decode(const int* __restrict__ raw_src, const int* __restrict__ raw_dst) {
    int i = blockIdx.x * 256 + threadIdx.x;
    if (i >= N_EDGES) return;
    int f = g_is64;
    g_src[i] = f ? raw_src[2 * i] : raw_src[i];
    g_dst[i] = f ? raw_dst[2 * i] : raw_dst[i];
}

// ---------------- zero kernels ----------------
__global__ void k_zero1() {
    int idx = blockIdx.x * 256 + threadIdx.x;            // 0..N*32-1
    g_bufB[idx] = make_float4(0.f, 0.f, 0.f, 0.f);
    if (idx < N_NODES) { g_deg_out[idx] = 0.f; g_deg_in[idx] = 0.f; }
}
__global__ void k_zero_agg2() {
    int idx = blockIdx.x * 256 + threadIdx.x;            // 0..N*16-1
    g_bufB[N_NODES * 16 + idx] = make_float4(0.f, 0.f, 0.f, 0.f);
}

// ---------------- degrees ----------------
__global__ void k_degree() {
    int e = blockIdx.x * 256 + threadIdx.x;
    if (e < N_EDGES) {
        atomicAdd(&g_deg_out[g_src[e]], 1.f);
        atomicAdd(&g_deg_in[g_dst[e]], 1.f);
    }
}
__global__ void k_finalize_deg() {
    int i = blockIdx.x * 256 + threadIdx.x;
    if (i < N_NODES) {
        g_deg_out[i] = rsqrtf(fmaxf(g_deg_out[i], 1.f));
        g_deg_in[i]  = rsqrtf(fmaxf(g_deg_in[i], 1.f));
    }
}

// ---------------- tiled fp32 GEMM with fused pre-epilogue on the A-load ----------------
// out[n,CD] = Aeff[n,KD] @ W, where
//   APOST=0: Aeff = A * rs[row]                      (rs may be null -> 1)
//   APOST=1: Aeff = relu(A*rin[row] + abias[col]) * rs[row]   (GCN layer-1 post, fused)
//   APOST=2: Aeff = (A*rin[row] + abias[col])                  (GCN layer-2 post, fused)
// WP1: W is Wp1[128,64]; effective B[k][j] = j<64 ? Wp1[k][j] : Wp1[64+k][j-64]
template<int KD, int CD, bool WP1, int APOST>
__global__ void k_gemm(const float* __restrict__ A, const float* __restrict__ W,
                       const float* __restrict__ rs, const float* __restrict__ rin,
                       const float* __restrict__ abias, float* __restrict__ out) {
    __shared__ float As[64 * 64];
    __shared__ float Bs[64 * CD];
    constexpr int CPT = CD / 32;
    int t = threadIdx.x;
    int row0 = blockIdx.x * 64;
    int tx = t & 31, ty = t >> 5;
    float acc[8][CPT] = {};

    for (int kc = 0; kc < KD; kc += 64) {
        // load A tile (64 rows x 64 k) with fused epilogue-of-previous-stage
        {
            int r = t >> 2, q = t & 3;
            int grow = row0 + r;
            bool ok = grow < N_NODES;
            float scale = ok ? (rs ? rs[grow] : 1.f) : 0.f;   // 0 zeroes padding rows
            float rin_v = (APOST != 0 && ok) ? rin[grow] : 0.f;
            const float4* ap = (const float4*)(A + (size_t)grow * KD + kc);
            const float4* bp = (const float4*)(abias + kc);
#pragma unroll
            for (int i = 0; i < 4; i++) {
                float4 v = make_float4(0.f, 0.f, 0.f, 0.f);
                if (ok) v = ap[q * 4 + i];
                if (APOST != 0) {
                    float4 bb = bp[q * 4 + i];           // bias indexed by k-column
                    v.x = v.x * rin_v + bb.x; v.y = v.y * rin_v + bb.y;
                    v.z = v.z * rin_v + bb.z; v.w = v.w * rin_v + bb.w;
                    if (APOST == 1) {
                        v.x = fmaxf(v.x, 0.f); v.y = fmaxf(v.y, 0.f);
                        v.z = fmaxf(v.z, 0.f); v.w = fmaxf(v.w, 0.f);
                    }
                }
                v.x *= scale; v.y *= scale; v.z *= scale; v.w *= scale;
                *(float4*)&As[r * 64 + q * 16 + i * 4] = v;
            }
        }
        // load B tile (64 k x CD)
        {
            constexpr int TOT4 = 64 * CD / 4;
            for (int idx = t; idx < TOT4; idx += 256) {
                float4 v;
                if (!WP1) {
                    v = ((const float4*)(W + (size_t)kc * CD))[idx];
                } else {
                    int k = (idx * 4) / CD, j = (idx * 4) % CD;
                    const float* p = (j < 64) ? (W + k * 64 + j) : (W + (64 + k) * 64 + (j - 64));
                    v = *(const float4*)p;
                }
                ((float4*)Bs)[idx] = v;
            }
        }
        __syncthreads();
#pragma unroll 4
        for (int k = 0; k < 64; k++) {
            float a[8];
#pragma unroll
            for (int i = 0; i < 8; i++) a[i] = As[(ty * 8 + i) * 64 + k];
            if constexpr (CPT == 4) {
                float4 b = *(const float4*)&Bs[k * CD + tx * 4];
#pragma unroll
                for (int i = 0; i < 8; i++) {
                    acc[i][0] += a[i] * b.x; acc[i][1] += a[i] * b.y;
                    acc[i][2] += a[i] * b.z; acc[i][3] += a[i] * b.w;
                }
            } else {
                float2 b = *(const float2*)&Bs[k * CD + tx * 2];
#pragma unroll
                for (int i = 0; i < 8; i++) {
                    acc[i][0] += a[i] * b.x; acc[i][1] += a[i] * b.y;
                }
            }
        }
        __syncthreads();
    }
#pragma unroll
    for (int i = 0; i < 8; i++) {
        int grow = row0 + ty * 8 + i;
        if (grow < N_NODES) {
            if constexpr (CPT == 4) {
                *(float4*)&out[(size_t)grow * CD + tx * 4] =
                    make_float4(acc[i][0], acc[i][1], acc[i][2], acc[i][3]);
            } else {
                *(float2*)&out[(size_t)grow * CD + tx * 2] = make_float2(acc[i][0], acc[i][1]);
            }
        }
    }
}

// ---------------- scatter-add: agg[dst] += h[src], C4 float4s per row ----------------
template<int C4>
__global__ void k_scatter(const float4* __restrict__ h, float4* __restrict__ agg) {
    int idx = blockIdx.x * 256 + threadIdx.x;
    if (idx >= N_EDGES * C4) return;
    int e = idx / C4, c = idx % C4;
    int s = g_src[e], d = g_dst[e];
    float4 v = h[(size_t)s * C4 + c];
    float4* p = agg + (size_t)d * C4 + c;
    asm volatile("red.global.add.v4.f32 [%0], {%1,%2,%3,%4};"
                 :: "l"(p), "f"(v.x), "f"(v.y), "f"(v.z), "f"(v.w) : "memory");
}

// ---------------- edge MLP: z1=relu(u[src]+v[dst]+b1); z2=relu(z1@Wp2+b2); sig(z2@Wp3+b3) ----------------
// uv here is ALREADY the final predictor-layer-1 pre-activation contribution per node:
// uv[n, 0:64] = h2[n]@Wp1_top, uv[n, 64:128] = h2[n]@Wp1_bot  (h2 includes +b2 via fused gemm)
__global__ void k_edge(const float4* __restrict__ uv, const float* __restrict__ bp1,
                       const float* __restrict__ Wp2, const float* __restrict__ bp2,
                       const float* __restrict__ Wp3, const float* __restrict__ bp3,
                       float* __restrict__ out) {
    __shared__ float z1s[64 * 68];
    __shared__ float w2s[64 * 32];
    __shared__ float b1s[64], b2s[32], w3s[32];
    int t = threadIdx.x;
    for (int i = t; i < 2048; i += 256) w2s[i] = Wp2[i];
    if (t < 64) b1s[t] = bp1[t];
    if (t < 32) { b2s[t] = bp2[t]; w3s[t] = Wp3[t]; }
    __syncthreads();

    int e0 = blockIdx.x * 64;
    // stage 1: gather + z1  (uv rows are 32 float4; u at 0..15, v at 16..31)
    {
        int el = t >> 2, q = t & 3;
        int e = e0 + el;
        int s = g_src[e], d = g_dst[e];
        const float4* up = uv + (size_t)s * 32;
        const float4* vp = uv + (size_t)d * 32 + 16;
#pragma unroll
        for (int i = 0; i < 4; i++) {
            int c4 = q * 4 + i;
            float4 a = up[c4], b = vp[c4];
            float4 z;
            z.x = fmaxf(a.x + b.x + b1s[c4 * 4 + 0], 0.f);
            z.y = fmaxf(a.y + b.y + b1s[c4 * 4 + 1], 0.f);
            z.z = fmaxf(a.z + b.z + b1s[c4 * 4 + 2], 0.f);
            z.w = fmaxf(a.w + b.w + b1s[c4 * 4 + 3], 0.f);
            *(float4*)&z1s[el * 68 + c4 * 4] = z;
        }
    }
    __syncthreads();
    // stage 2: z2 + score; thread = (edge-pair, 4 cols)
    int jg = t & 7, eg = t >> 3;
    int ebase = eg * 2;
    float acc0[4], acc1[4];
#pragma unroll
    for (int j = 0; j < 4; j++) { acc0[j] = b2s[jg * 4 + j]; acc1[j] = acc0[j]; }
    const float* z0 = &z1s[ebase * 68];
    const float* z1p = &z1s[(ebase + 1) * 68];
#pragma unroll 8
    for (int k = 0; k < 64; k++) {
        float za = z0[k], zb = z1p[k];
        float4 w = *(const float4*)&w2s[k * 32 + jg * 4];
        acc0[0] += za * w.x; acc0[1] += za * w.y; acc0[2] += za * w.z; acc0[3] += za * w.w;
        acc1[0] += zb * w.x; acc1[1] += zb * w.y; acc1[2] += zb * w.z; acc1[3] += zb * w.w;
    }
    float p0 = 0.f, p1 = 0.f;
#pragma unroll
    for (int j = 0; j < 4; j++) {
        p0 += fmaxf(acc0[j], 0.f) * w3s[jg * 4 + j];
        p1 += fmaxf(acc1[j], 0.f) * w3s[jg * 4 + j];
    }
#pragma unroll
    for (int off = 4; off; off >>= 1) {
        p0 += __shfl_down_sync(0xffffffffu, p0, off, 8);
        p1 += __shfl_down_sync(0xffffffffu, p1, off, 8);
    }
    if (jg == 0) {
        float b3 = bp3[0];
        out[e0 + ebase]     = 1.f / (1.f + __expf(-(p0 + b3)));
        out[e0 + ebase + 1] = 1.f / (1.f + __expf(-(p1 + b3)));
    }
}

extern "C" void kernel_launch(void* const* d_in, const int* in_sizes, int n_in,
                              void* d_out, int out_size) {
    const float* x       = (const float*)d_in[0];
    const int*   raw_src = (const int*)d_in[1];   // int32 OR int64 storage; probed on device
    const int*   raw_dst = (const int*)d_in[2];
    const float* W1  = (const float*)d_in[3];
    const float* b1  = (const float*)d_in[4];
    const float* W2  = (const float*)d_in[5];
    const float* b2  = (const float*)d_in[6];
    const float* Wp1 = (const float*)d_in[7];
    const float* bp1 = (const float*)d_in[8];
    const float* Wp2 = (const float*)d_in[9];
    const float* bp2 = (const float*)d_in[10];
    const float* Wp3 = (const float*)d_in[11];
    const float* bp3 = (const float*)d_in[12];
    float* out = (float*)d_out;

    float4 *bufA, *bufB;
    float *invOut, *invIn;
    cudaGetSymbolAddress((void**)&bufA, g_bufA);
    cudaGetSymbolAddress((void**)&bufB, g_bufB);
    cudaGetSymbolAddress((void**)&invOut, g_deg_out);
    cudaGetSymbolAddress((void**)&invIn, g_deg_in);

    const int NB_GEMM = (N_NODES + 63) / 64;   // 1563

    // index decode (dtype-agnostic) + degrees + zero agg1
    k_probe<<<1, 256>>>(raw_src, raw_dst);
    k_decode<<<(N_EDGES + 255) / 256, 256>>>(raw_src, raw_dst);
    k_zero1<<<N_NODES * 32 / 256, 256>>>();
    k_degree<<<(N_EDGES + 255) / 256, 256>>>();
    k_finalize_deg<<<(N_NODES + 255) / 256, 256>>>();

    // layer 1: h1pre = (x*rs_out) @ W1 ; agg1 = scatter(h1pre)
    k_gemm<128, 128, false, 0><<<NB_GEMM, 256>>>(x, W1, invOut, nullptr, nullptr, (float*)bufA);
    k_scatter<32><<<(N_EDGES * 32 + 255) / 256, 256>>>(bufA, bufB);

    // layer 2 (fused post): h2pre = (relu(agg1*rin + b1) * rs_out) @ W2
    k_gemm<128, 64, false, 1><<<NB_GEMM, 256>>>((const float*)bufB, W2, invOut, invIn, b1,
                                                (float*)bufA);
    k_zero_agg2<<<N_NODES * 16 / 256, 256>>>();      // after gemm2 consumed agg1's upper half
    k_scatter<16><<<(N_EDGES * 16 + 255) / 256, 256>>>(bufA, bufB + N_NODES * 16);

    // predictor (fused post): uv = (agg2*rin + b2) @ [Wp1_top | Wp1_bot]
    k_gemm<64, 128, true, 2><<<NB_GEMM, 256>>>((const float*)(bufB + N_NODES * 16), Wp1,
                                               nullptr, invIn, b2, (float*)bufA);

    // edge MLP
    k_edge<<<N_EDGES / 64, 256>>>(bufA, bp1, Wp2, bp2, Wp3, bp3, out);
}

// round 16
// speedup vs baseline: 1.0221x; 1.0221x over previous
#include <cuda_runtime.h>
#include <cuda_bf16.h>

#define N_NODES 100000
#define N_EDGES 1600000

typedef unsigned long long u64;

// scratch (allocation-free rule: __device__ globals). float4-typed => 16B aligned.
__device__ float4 g_bufA[N_NODES * 32];   // 128 floats per node
__device__ float4 g_bufB[N_NODES * 32];
__device__ float  g_deg_out[N_NODES];
__device__ float  g_deg_in[N_NODES];
__device__ int    g_src[N_EDGES];         // decoded int32 indices
__device__ int    g_dst[N_EDGES];
__device__ int    g_is64;

// ---- packed f32x2 helpers (sm_103a; bit-exact fp32 per lane) ----
__device__ __forceinline__ void ffma2(u64& d, u64 a, u64 b) {
    asm("fma.rn.f32x2 %0, %1, %2, %0;" : "+l"(d) : "l"(a), "l"(b));
}
__device__ __forceinline__ u64 pk2(float lo, float hi) {
    u64 r; asm("mov.b64 %0, {%1,%2};" : "=l"(r) : "f"(lo), "f"(hi)); return r;
}
__device__ __forceinline__ float2 upk2(u64 v) {
    float2 r; asm("mov.b64 {%0,%1}, %2;" : "=f"(r.x), "=f"(r.y) : "l"(v)); return r;
}

// ---------------- index dtype probe + decode ----------------
__global__ void k_probe(const int* __restrict__ raw_src, const int* __restrict__ raw_dst) {
    __shared__ int any;
    if (threadIdx.x == 0) any = 0;
    __syncthreads();
    int t = threadIdx.x;
    int acc = 0;
    for (int i = 0; i < 4; i++) {
        int w = 2 * (t + i * 256) + 1;
        acc |= raw_src[w] | raw_dst[w];
    }
    if (acc) atomicOr(&any, 1);
    __syncthreads();
    if (threadIdx.x == 0) g_is64 = (any == 0);
}
__global__ void k_decode(const int* __restrict__ raw_src, const int* __restrict__ raw_dst) {
    int i = blockIdx.x * 256 + threadIdx.x;
    if (i >= N_EDGES) return;
    int f = g_is64;
    g_src[i] = f ? raw_src[2 * i] : raw_src[i];
    g_dst[i] = f ? raw_dst[2 * i] : raw_dst[i];
}

// ---------------- zero kernels ----------------
__global__ void k_zero1() {
    int idx = blockIdx.x * 256 + threadIdx.x;            // 0..N*32-1
    g_bufB[idx] = make_float4(0.f, 0.f, 0.f, 0.f);
    if (idx < N_NODES) { g_deg_out[idx] = 0.f; g_deg_in[idx] = 0.f; }
}
__global__ void k_zero_agg2() {
    int idx = blockIdx.x * 256 + threadIdx.x;            // 0..N*16-1
    g_bufB[N_NODES * 16 + idx] = make_float4(0.f, 0.f, 0.f, 0.f);
}

// ---------------- degrees ----------------
__global__ void k_degree() {
    int e = blockIdx.x * 256 + threadIdx.x;
    if (e < N_EDGES) {
        atomicAdd(&g_deg_out[g_src[e]], 1.f);
        atomicAdd(&g_deg_in[g_dst[e]], 1.f);
    }
}
__global__ void k_finalize_deg() {
    int i = blockIdx.x * 256 + threadIdx.x;
    if (i < N_NODES) {
        g_deg_out[i] = rsqrtf(fmaxf(g_deg_out[i], 1.f));
        g_deg_in[i]  = rsqrtf(fmaxf(g_deg_in[i], 1.f));
    }
}

// ---------------- tiled fp32 GEMM (f32x2 mainloop) with fused pre-epilogue ----------------
// out[n,CD] = Aeff[n,KD] @ W
//   APOST=0: Aeff = A * rs[row]
//   APOST=1: Aeff = relu(A*rin[row] + abias[col]) * rs[row]
//   APOST=2: Aeff = (A*rin[row] + abias[col])
// WP1: W is Wp1[128,64]; effective B[k][j] = j<64 ? Wp1[k][j] : Wp1[64+k][j-64]
// As is stored K-MAJOR: As[k*64 + row] so row-pairs read as broadcast LDS.64 f32x2.
template<int KD, int CD, bool WP1, int APOST>
__global__ void k_gemm(const float* __restrict__ A, const float* __restrict__ W,
                       const float* __restrict__ rs, const float* __restrict__ rin,
                       const float* __restrict__ abias, float* __restrict__ out) {
    __shared__ float As[64 * 64];      // [k][row]
    __shared__ float Bs[64 * CD];      // [k][col]
    constexpr int CPT = CD / 32;
    int t = threadIdx.x;
    int row0 = blockIdx.x * 64;
    int tx = t & 31, ty = t >> 5;
    u64 acc2[4][CPT];                  // [row-pair][col], each = {out[row2p], out[row2p+1]}
#pragma unroll
    for (int p = 0; p < 4; p++)
#pragma unroll
        for (int j = 0; j < CPT; j++) acc2[p][j] = 0ULL;

    for (int kc = 0; kc < KD; kc += 64) {
        // load A tile (64 rows x 64 k) with fused epilogue, store k-major
        {
            int r = t >> 2, q = t & 3;
            int grow = row0 + r;
            bool ok = grow < N_NODES;
            float scale = ok ? (rs ? rs[grow] : 1.f) : 0.f;
            float rin_v = (APOST != 0 && ok) ? rin[grow] : 0.f;
            const float4* ap = (const float4*)(A + (size_t)grow * KD + kc);
            const float4* bp = (const float4*)(abias + kc);
#pragma unroll
            for (int i = 0; i < 4; i++) {
                float4 v = make_float4(0.f, 0.f, 0.f, 0.f);
                if (ok) v = ap[q * 4 + i];
                if (APOST != 0) {
                    float4 bb = bp[q * 4 + i];
                    v.x = v.x * rin_v + bb.x; v.y = v.y * rin_v + bb.y;
                    v.z = v.z * rin_v + bb.z; v.w = v.w * rin_v + bb.w;
                    if (APOST == 1) {
                        v.x = fmaxf(v.x, 0.f); v.y = fmaxf(v.y, 0.f);
                        v.z = fmaxf(v.z, 0.f); v.w = fmaxf(v.w, 0.f);
                    }
                }
                v.x *= scale; v.y *= scale; v.z *= scale; v.w *= scale;
                int kk = q * 16 + i * 4;
                As[(kk + 0) * 64 + r] = v.x;
                As[(kk + 1) * 64 + r] = v.y;
                As[(kk + 2) * 64 + r] = v.z;
                As[(kk + 3) * 64 + r] = v.w;
            }
        }
        // load B tile (64 k x CD)
        {
            constexpr int TOT4 = 64 * CD / 4;
            for (int idx = t; idx < TOT4; idx += 256) {
                float4 v;
                if (!WP1) {
                    v = ((const float4*)(W + (size_t)kc * CD))[idx];
                } else {
                    int k = (idx * 4) / CD, j = (idx * 4) % CD;
                    const float* p = (j < 64) ? (W + k * 64 + j) : (W + (64 + k) * 64 + (j - 64));
                    v = *(const float4*)p;
                }
                ((float4*)Bs)[idx] = v;
            }
        }
        __syncthreads();
        const u64* As2 = (const u64*)As;
#pragma unroll 4
        for (int k = 0; k < 64; k++) {
            u64 a2[4];
#pragma unroll
            for (int p = 0; p < 4; p++) a2[p] = As2[k * 32 + ty * 4 + p];  // warp-uniform
            if constexpr (CPT == 4) {
                float4 b = *(const float4*)&Bs[k * CD + tx * 4];
                u64 b0 = pk2(b.x, b.x), b1 = pk2(b.y, b.y);
                u64 b2v = pk2(b.z, b.z), b3 = pk2(b.w, b.w);
#pragma unroll
                for (int p = 0; p < 4; p++) {
                    ffma2(acc2[p][0], a2[p], b0); ffma2(acc2[p][1], a2[p], b1);
                    ffma2(acc2[p][2], a2[p], b2v); ffma2(acc2[p][3], a2[p], b3);
                }
            } else {
                float2 b = *(const float2*)&Bs[k * CD + tx * 2];
                u64 b0 = pk2(b.x, b.x), b1 = pk2(b.y, b.y);
#pragma unroll
                for (int p = 0; p < 4; p++) {
                    ffma2(acc2[p][0], a2[p], b0); ffma2(acc2[p][1], a2[p], b1);
                }
            }
        }
        __syncthreads();
    }
#pragma unroll
    for (int p = 0; p < 4; p++) {
        int grow = row0 + ty * 8 + 2 * p;
        if constexpr (CPT == 4) {
            float2 e0 = upk2(acc2[p][0]), e1 = upk2(acc2[p][1]);
            float2 e2 = upk2(acc2[p][2]), e3 = upk2(acc2[p][3]);
            if (grow < N_NODES)
                *(float4*)&out[(size_t)grow * CD + tx * 4] = make_float4(e0.x, e1.x, e2.x, e3.x);
            if (grow + 1 < N_NODES)
                *(float4*)&out[(size_t)(grow + 1) * CD + tx * 4] = make_float4(e0.y, e1.y, e2.y, e3.y);
        } else {
            float2 e0 = upk2(acc2[p][0]), e1 = upk2(acc2[p][1]);
            if (grow < N_NODES)
                *(float2*)&out[(size_t)grow * CD + tx * 2] = make_float2(e0.x, e1.x);
            if (grow + 1 < N_NODES)
                *(float2*)&out[(size_t)(grow + 1) * CD + tx * 2] = make_float2(e0.y, e1.y);
        }
    }
}

// ---------------- scatter-add: agg[dst] += h[src], C4 float4s per row ----------------
template<int C4>
__global__ void k_scatter(const float4* __restrict__ h, float4* __restrict__ agg) {
    int idx = blockIdx.x * 256 + threadIdx.x;
    if (idx >= N_EDGES * C4) return;
    int e = idx / C4, c = idx % C4;
    int s = g_src[e], d = g_dst[e];
    float4 v = h[(size_t)s * C4 + c];
    float4* p = agg + (size_t)d * C4 + c;
    asm volatile("red.global.add.v4.f32 [%0], {%1,%2,%3,%4};"
                 :: "l"(p), "f"(v.x), "f"(v.y), "f"(v.z), "f"(v.w) : "memory");
}

// ---------------- edge MLP (f32x2 stage 2) ----------------
// uv[n,0:64]=h2[n]@Wp1_top, uv[n,64:128]=h2[n]@Wp1_bot (h2 incl. +b2 via fused gemm)
__global__ void k_edge(const float4* __restrict__ uv, const float* __restrict__ bp1,
                       const float* __restrict__ Wp2, const float* __restrict__ bp2,
                       const float* __restrict__ Wp3, const float* __restrict__ bp3,
                       float* __restrict__ out) {
    __shared__ float z1s[64 * 68];
    __shared__ float w2s[64 * 32];
    __shared__ float b1s[64], b2s[32], w3s[32];
    int t = threadIdx.x;
    for (int i = t; i < 2048; i += 256) w2s[i] = Wp2[i];
    if (t < 64) b1s[t] = bp1[t];
    if (t < 32) { b2s[t] = bp2[t]; w3s[t] = Wp3[t]; }
    __syncthreads();

    int e0 = blockIdx.x * 64;
    // stage 1: gather + z1
    {
        int el = t >> 2, q = t & 3;
        int e = e0 + el;
        int s = g_src[e], d = g_dst[e];
        const float4* up = uv + (size_t)s * 32;
        const float4* vp = uv + (size_t)d * 32 + 16;
#pragma unroll
        for (int i = 0; i < 4; i++) {
            int c4 = q * 4 + i;
            float4 a = up[c4], b = vp[c4];
            float4 z;
            z.x = fmaxf(a.x + b.x + b1s[c4 * 4 + 0], 0.f);
            z.y = fmaxf(a.y + b.y + b1s[c4 * 4 + 1], 0.f);
            z.z = fmaxf(a.z + b.z + b1s[c4 * 4 + 2], 0.f);
            z.w = fmaxf(a.w + b.w + b1s[c4 * 4 + 3], 0.f);
            *(float4*)&z1s[el * 68 + c4 * 4] = z;
        }
    }
    __syncthreads();
    // stage 2: z2 + score; thread = (edge-pair, 4 cols); accumulate j-pairs as f32x2
    int jg = t & 7, eg = t >> 3;
    int ebase = eg * 2;
    u64 accA[2], accB[2];
    accA[0] = pk2(b2s[jg * 4 + 0], b2s[jg * 4 + 1]);
    accA[1] = pk2(b2s[jg * 4 + 2], b2s[jg * 4 + 3]);
    accB[0] = accA[0]; accB[1] = accA[1];
    const float* z0 = &z1s[ebase * 68];
    const float* z1p = &z1s[(ebase + 1) * 68];
#pragma unroll 8
    for (int k = 0; k < 64; k++) {
        u64 za2 = pk2(z0[k], z0[k]);
        u64 zb2 = pk2(z1p[k], z1p[k]);
        ulonglong2 wv = *(const ulonglong2*)&w2s[k * 32 + jg * 4];  // {w0,w1},{w2,w3}
        ffma2(accA[0], za2, wv.x); ffma2(accA[1], za2, wv.y);
        ffma2(accB[0], zb2, wv.x); ffma2(accB[1], zb2, wv.y);
    }
    float2 a01 = upk2(accA[0]), a23 = upk2(accA[1]);
    float2 b01 = upk2(accB[0]), b23 = upk2(accB[1]);
    float p0 = fmaxf(a01.x, 0.f) * w3s[jg * 4 + 0] + fmaxf(a01.y, 0.f) * w3s[jg * 4 + 1]
             + fmaxf(a23.x, 0.f) * w3s[jg * 4 + 2] + fmaxf(a23.y, 0.f) * w3s[jg * 4 + 3];
    float p1 = fmaxf(b01.x, 0.f) * w3s[jg * 4 + 0] + fmaxf(b01.y, 0.f) * w3s[jg * 4 + 1]
             + fmaxf(b23.x, 0.f) * w3s[jg * 4 + 2] + fmaxf(b23.y, 0.f) * w3s[jg * 4 + 3];
#pragma unroll
    for (int off = 4; off; off >>= 1) {
        p0 += __shfl_down_sync(0xffffffffu, p0, off, 8);
        p1 += __shfl_down_sync(0xffffffffu, p1, off, 8);
    }
    if (jg == 0) {
        float b3 = bp3[0];
        out[e0 + ebase]     = 1.f / (1.f + __expf(-(p0 + b3)));
        out[e0 + ebase + 1] = 1.f / (1.f + __expf(-(p1 + b3)));
    }
}

extern "C" void kernel_launch(void* const* d_in, const int* in_sizes, int n_in,
                              void* d_out, int out_size) {
    const float* x       = (const float*)d_in[0];
    const int*   raw_src = (const int*)d_in[1];   // int32 OR int64 storage; probed on device
    const int*   raw_dst = (const int*)d_in[2];
    const float* W1  = (const float*)d_in[3];
    const float* b1  = (const float*)d_in[4];
    const float* W2  = (const float*)d_in[5];
    const float* b2  = (const float*)d_in[6];
    const float* Wp1 = (const float*)d_in[7];
    const float* bp1 = (const float*)d_in[8];
    const float* Wp2 = (const float*)d_in[9];
    const float* bp2 = (const float*)d_in[10];
    const float* Wp3 = (const float*)d_in[11];
    const float* bp3 = (const float*)d_in[12];
    float* out = (float*)d_out;

    float4 *bufA, *bufB;
    float *invOut, *invIn;
    cudaGetSymbolAddress((void**)&bufA, g_bufA);
    cudaGetSymbolAddress((void**)&bufB, g_bufB);
    cudaGetSymbolAddress((void**)&invOut, g_deg_out);
    cudaGetSymbolAddress((void**)&invIn, g_deg_in);

    const int NB_GEMM = (N_NODES + 63) / 64;   // 1563

    // index decode (dtype-agnostic) + degrees + zero agg1
    k_probe<<<1, 256>>>(raw_src, raw_dst);
    k_decode<<<(N_EDGES + 255) / 256, 256>>>(raw_src, raw_dst);
    k_zero1<<<N_NODES * 32 / 256, 256>>>();
    k_degree<<<(N_EDGES + 255) / 256, 256>>>();
    k_finalize_deg<<<(N_NODES + 255) / 256, 256>>>();

    // layer 1: h1pre = (x*rs_out) @ W1 ; agg1 = scatter(h1pre)
    k_gemm<128, 128, false, 0><<<NB_GEMM, 256>>>(x, W1, invOut, nullptr, nullptr, (float*)bufA);
    k_scatter<32><<<(N_EDGES * 32 + 255) / 256, 256>>>(bufA, bufB);

    // layer 2 (fused post): h2pre = (relu(agg1*rin + b1) * rs_out) @ W2
    k_gemm<128, 64, false, 1><<<NB_GEMM, 256>>>((const float*)bufB, W2, invOut, invIn, b1,
                                                (float*)bufA);
    k_zero_agg2<<<N_NODES * 16 / 256, 256>>>();
    k_scatter<16><<<(N_EDGES * 16 + 255) / 256, 256>>>(bufA, bufB + N_NODES * 16);

    // predictor (fused post): uv = (agg2*rin + b2) @ [Wp1_top | Wp1_bot]
    k_gemm<64, 128, true, 2><<<NB_GEMM, 256>>>((const float*)(bufB + N_NODES * 16), Wp1,
                                               nullptr, invIn, b2, (float*)bufA);

    // edge MLP
    k_edge<<<N_EDGES / 64, 256>>>(bufA, bp1, Wp2, bp2, Wp3, bp3, out);
}

// round 17
// speedup vs baseline: 1.2748x; 1.2472x over previous
#include <cuda_runtime.h>
#include <cuda_bf16.h>

#define N_NODES 100000
#define N_EDGES 1600000
#define SCAN_B 391   // ceil(100000/256)

typedef unsigned long long u64;

// scratch (allocation-free rule: __device__ globals). float4-typed => 16B aligned.
__device__ float4 g_bufA[N_NODES * 32];   // 128 floats per node
__device__ float4 g_bufB[N_NODES * 32];
__device__ float  g_deg_out[N_NODES];
__device__ float  g_deg_in[N_NODES];
__device__ int    g_src[N_EDGES];         // decoded int32 indices (original order)
__device__ int    g_dst[N_EDGES];
__device__ int    g_ssrc[N_EDGES];        // src of edges sorted by dst
__device__ int    g_cnt_in[N_NODES];
__device__ int    g_cnt_out[N_NODES];
__device__ int    g_offs[N_NODES];        // exclusive prefix sum of cnt_in
__device__ int    g_cursor[N_NODES];
__device__ int    g_blk[512];
__device__ int    g_is64;

// ---- packed f32x2 helpers (sm_103a; bit-exact fp32 per lane) ----
__device__ __forceinline__ void ffma2(u64& d, u64 a, u64 b) {
    asm("fma.rn.f32x2 %0, %1, %2, %0;" : "+l"(d) : "l"(a), "l"(b));
}
__device__ __forceinline__ u64 pk2(float lo, float hi) {
    u64 r; asm("mov.b64 %0, {%1,%2};" : "=l"(r) : "f"(lo), "f"(hi)); return r;
}
__device__ __forceinline__ float2 upk2(u64 v) {
    float2 r; asm("mov.b64 {%0,%1}, %2;" : "=f"(r.x), "=f"(r.y) : "l"(v)); return r;
}

// ---------------- index dtype probe + decode ----------------
__global__ void k_probe(const int* __restrict__ raw_src, const int* __restrict__ raw_dst) {
    __shared__ int any;
    if (threadIdx.x == 0) any = 0;
    __syncthreads();
    int t = threadIdx.x;
    int acc = 0;
    for (int i = 0; i < 4; i++) {
        int w = 2 * (t + i * 256) + 1;
        acc |= raw_src[w] | raw_dst[w];
    }
    if (acc) atomicOr(&any, 1);
    __syncthreads();
    if (threadIdx.x == 0) g_is64 = (any == 0);
}
__global__ void k_decode(const int* __restrict__ raw_src, const int* __restrict__ raw_dst) {
    int i = blockIdx.x * 256 + threadIdx.x;
    if (i >= N_EDGES) return;
    int f = g_is64;
    g_src[i] = f ? raw_src[2 * i] : raw_src[i];
    g_dst[i] = f ? raw_dst[2 * i] : raw_dst[i];
}

// ---------------- init + histogram + degrees ----------------
__global__ void k_init() {
    int i = blockIdx.x * 256 + threadIdx.x;
    if (i < N_NODES) { g_cnt_in[i] = 0; g_cnt_out[i] = 0; g_cursor[i] = 0; }
}
__global__ void k_hist() {
    int e = blockIdx.x * 256 + threadIdx.x;
    if (e < N_EDGES) {
        atomicAdd(&g_cnt_out[g_src[e]], 1);
        atomicAdd(&g_cnt_in[g_dst[e]], 1);
    }
}
__global__ void k_finalize_deg() {
    int i = blockIdx.x * 256 + threadIdx.x;
    if (i < N_NODES) {
        g_deg_out[i] = rsqrtf((float)max(g_cnt_out[i], 1));
        g_deg_in[i]  = rsqrtf((float)max(g_cnt_in[i], 1));
    }
}

// ---------------- prefix sum over cnt_in (3 kernels) ----------------
__global__ void k_scan1() {
    __shared__ int sd[256];
    int t = threadIdx.x, b = blockIdx.x;
    int i = b * 256 + t;
    int c = (i < N_NODES) ? g_cnt_in[i] : 0;
    sd[t] = c; __syncthreads();
#pragma unroll
    for (int off = 1; off < 256; off <<= 1) {
        int v = (t >= off) ? sd[t - off] : 0;
        __syncthreads();
        sd[t] += v;
        __syncthreads();
    }
    if (i < N_NODES) g_offs[i] = sd[t] - c;     // block-local exclusive
    if (t == 255) g_blk[b] = sd[255];           // block total
}
__global__ void k_scan2() {
    __shared__ int sd[512];
    int t = threadIdx.x;
    int c = (t < SCAN_B) ? g_blk[t] : 0;
    sd[t] = c; __syncthreads();
#pragma unroll
    for (int off = 1; off < 512; off <<= 1) {
        int v = (t >= off) ? sd[t - off] : 0;
        __syncthreads();
        sd[t] += v;
        __syncthreads();
    }
    if (t < SCAN_B) g_blk[t] = sd[t] - c;       // exclusive block offsets
}
__global__ void k_scan3() {
    int i = blockIdx.x * 256 + threadIdx.x;
    if (i < N_NODES) g_offs[i] += g_blk[blockIdx.x];
}

// ---------------- placement: bucket edges by dst ----------------
__global__ void k_place() {
    int e = blockIdx.x * 256 + threadIdx.x;
    if (e < N_EDGES) {
        int d = g_dst[e];
        int pos = g_offs[d] + atomicAdd(&g_cursor[d], 1);
        g_ssrc[pos] = g_src[e];
    }
}

// ---------------- atomic-free aggregation: agg[n] = sum_{e: dst=n} h[src[e]] ----------------
// C4F4 variant: rows of 32 float4 (128 floats). One warp per node.
__global__ void k_agg32(const float4* __restrict__ h, float4* __restrict__ agg) {
    int t = threadIdx.x;
    int n = blockIdx.x * 8 + (t >> 5);
    int lane = t & 31;
    if (n >= N_NODES) return;
    int start = g_offs[n], end = start + g_cnt_in[n];
    float4 acc = make_float4(0.f, 0.f, 0.f, 0.f);
    for (int i = start; i < end; i++) {
        int s = g_ssrc[i];                      // warp-uniform broadcast
        float4 v = h[(size_t)s * 32 + lane];
        acc.x += v.x; acc.y += v.y; acc.z += v.z; acc.w += v.w;
    }
    agg[(size_t)n * 32 + lane] = acc;
}
// rows of 32 float2 (64 floats). One warp per node.
__global__ void k_agg16(const float2* __restrict__ h, float2* __restrict__ agg) {
    int t = threadIdx.x;
    int n = blockIdx.x * 8 + (t >> 5);
    int lane = t & 31;
    if (n >= N_NODES) return;
    int start = g_offs[n], end = start + g_cnt_in[n];
    float2 acc = make_float2(0.f, 0.f);
    for (int i = start; i < end; i++) {
        int s = g_ssrc[i];
        float2 v = h[(size_t)s * 32 + lane];
        acc.x += v.x; acc.y += v.y;
    }
    agg[(size_t)n * 32 + lane] = acc;
}

// ---------------- tiled fp32 GEMM (f32x2 mainloop) with fused pre-epilogue ----------------
// out[n,CD] = Aeff[n,KD] @ W
//   APOST=0: Aeff = A * rs[row]
//   APOST=1: Aeff = relu(A*rin[row] + abias[col]) * rs[row]
//   APOST=2: Aeff = (A*rin[row] + abias[col])
// WP1: W is Wp1[128,64]; effective B[k][j] = j<64 ? Wp1[k][j] : Wp1[64+k][j-64]
template<int KD, int CD, bool WP1, int APOST>
__global__ void k_gemm(const float* __restrict__ A, const float* __restrict__ W,
                       const float* __restrict__ rs, const float* __restrict__ rin,
                       const float* __restrict__ abias, float* __restrict__ out) {
    __shared__ float As[64 * 64];      // [k][row]
    __shared__ float Bs[64 * CD];      // [k][col]
    constexpr int CPT = CD / 32;
    int t = threadIdx.x;
    int row0 = blockIdx.x * 64;
    int tx = t & 31, ty = t >> 5;
    u64 acc2[4][CPT];
#pragma unroll
    for (int p = 0; p < 4; p++)
#pragma unroll
        for (int j = 0; j < CPT; j++) acc2[p][j] = 0ULL;

    for (int kc = 0; kc < KD; kc += 64) {
        {
            int r = t >> 2, q = t & 3;
            int grow = row0 + r;
            bool ok = grow < N_NODES;
            float scale = ok ? (rs ? rs[grow] : 1.f) : 0.f;
            float rin_v = (APOST != 0 && ok) ? rin[grow] : 0.f;
            const float4* ap = (const float4*)(A + (size_t)grow * KD + kc);
            const float4* bp = (const float4*)(abias + kc);
#pragma unroll
            for (int i = 0; i < 4; i++) {
                float4 v = make_float4(0.f, 0.f, 0.f, 0.f);
                if (ok) v = ap[q * 4 + i];
                if (APOST != 0) {
                    float4 bb = bp[q * 4 + i];
                    v.x = v.x * rin_v + bb.x; v.y = v.y * rin_v + bb.y;
                    v.z = v.z * rin_v + bb.z; v.w = v.w * rin_v + bb.w;
                    if (APOST == 1) {
                        v.x = fmaxf(v.x, 0.f); v.y = fmaxf(v.y, 0.f);
                        v.z = fmaxf(v.z, 0.f); v.w = fmaxf(v.w, 0.f);
                    }
                }
                v.x *= scale; v.y *= scale; v.z *= scale; v.w *= scale;
                int kk = q * 16 + i * 4;
                As[(kk + 0) * 64 + r] = v.x;
                As[(kk + 1) * 64 + r] = v.y;
                As[(kk + 2) * 64 + r] = v.z;
                As[(kk + 3) * 64 + r] = v.w;
            }
        }
        {
            constexpr int TOT4 = 64 * CD / 4;
            for (int idx = t; idx < TOT4; idx += 256) {
                float4 v;
                if (!WP1) {
                    v = ((const float4*)(W + (size_t)kc * CD))[idx];
                } else {
                    int k = (idx * 4) / CD, j = (idx * 4) % CD;
                    const float* p = (j < 64) ? (W + k * 64 + j) : (W + (64 + k) * 64 + (j - 64));
                    v = *(const float4*)p;
                }
                ((float4*)Bs)[idx] = v;
            }
        }
        __syncthreads();
        const u64* As2 = (const u64*)As;
#pragma unroll 4
        for (int k = 0; k < 64; k++) {
            u64 a2[4];
#pragma unroll
            for (int p = 0; p < 4; p++) a2[p] = As2[k * 32 + ty * 4 + p];
            if constexpr (CPT == 4) {
                float4 b = *(const float4*)&Bs[k * CD + tx * 4];
                u64 b0 = pk2(b.x, b.x), b1 = pk2(b.y, b.y);
                u64 b2v = pk2(b.z, b.z), b3 = pk2(b.w, b.w);
#pragma unroll
                for (int p = 0; p < 4; p++) {
                    ffma2(acc2[p][0], a2[p], b0); ffma2(acc2[p][1], a2[p], b1);
                    ffma2(acc2[p][2], a2[p], b2v); ffma2(acc2[p][3], a2[p], b3);
                }
            } else {
                float2 b = *(const float2*)&Bs[k * CD + tx * 2];
                u64 b0 = pk2(b.x, b.x), b1 = pk2(b.y, b.y);
#pragma unroll
                for (int p = 0; p < 4; p++) {
                    ffma2(acc2[p][0], a2[p], b0); ffma2(acc2[p][1], a2[p], b1);
                }
            }
        }
        __syncthreads();
    }
#pragma unroll
    for (int p = 0; p < 4; p++) {
        int grow = row0 + ty * 8 + 2 * p;
        if constexpr (CPT == 4) {
            float2 e0 = upk2(acc2[p][0]), e1 = upk2(acc2[p][1]);
            float2 e2 = upk2(acc2[p][2]), e3 = upk2(acc2[p][3]);
            if (grow < N_NODES)
                *(float4*)&out[(size_t)grow * CD + tx * 4] = make_float4(e0.x, e1.x, e2.x, e3.x);
            if (grow + 1 < N_NODES)
                *(float4*)&out[(size_t)(grow + 1) * CD + tx * 4] = make_float4(e0.y, e1.y, e2.y, e3.y);
        } else {
            float2 e0 = upk2(acc2[p][0]), e1 = upk2(acc2[p][1]);
            if (grow < N_NODES)
                *(float2*)&out[(size_t)grow * CD + tx * 2] = make_float2(e0.x, e1.x);
            if (grow + 1 < N_NODES)
                *(float2*)&out[(size_t)(grow + 1) * CD + tx * 2] = make_float2(e0.y, e1.y);
        }
    }
}

// ---------------- edge MLP (f32x2 stage 2) ----------------
__global__ void k_edge(const float4* __restrict__ uv, const float* __restrict__ bp1,
                       const float* __restrict__ Wp2, const float* __restrict__ bp2,
                       const float* __restrict__ Wp3, const float* __restrict__ bp3,
                       float* __restrict__ out) {
    __shared__ float z1s[64 * 68];
    __shared__ float w2s[64 * 32];
    __shared__ float b1s[64], b2s[32], w3s[32];
    int t = threadIdx.x;
    for (int i = t; i < 2048; i += 256) w2s[i] = Wp2[i];
    if (t < 64) b1s[t] = bp1[t];
    if (t < 32) { b2s[t] = bp2[t]; w3s[t] = Wp3[t]; }
    __syncthreads();

    int e0 = blockIdx.x * 64;
    {
        int el = t >> 2, q = t & 3;
        int e = e0 + el;
        int s = g_src[e], d = g_dst[e];
        const float4* up = uv + (size_t)s * 32;
        const float4* vp = uv + (size_t)d * 32 + 16;
#pragma unroll
        for (int i = 0; i < 4; i++) {
            int c4 = q * 4 + i;
            float4 a = up[c4], b = vp[c4];
            float4 z;
            z.x = fmaxf(a.x + b.x + b1s[c4 * 4 + 0], 0.f);
            z.y = fmaxf(a.y + b.y + b1s[c4 * 4 + 1], 0.f);
            z.z = fmaxf(a.z + b.z + b1s[c4 * 4 + 2], 0.f);
            z.w = fmaxf(a.w + b.w + b1s[c4 * 4 + 3], 0.f);
            *(float4*)&z1s[el * 68 + c4 * 4] = z;
        }
    }
    __syncthreads();
    int jg = t & 7, eg = t >> 3;
    int ebase = eg * 2;
    u64 accA[2], accB[2];
    accA[0] = pk2(b2s[jg * 4 + 0], b2s[jg * 4 + 1]);
    accA[1] = pk2(b2s[jg * 4 + 2], b2s[jg * 4 + 3]);
    accB[0] = accA[0]; accB[1] = accA[1];
    const float* z0 = &z1s[ebase * 68];
    const float* z1p = &z1s[(ebase + 1) * 68];
#pragma unroll 8
    for (int k = 0; k < 64; k++) {
        u64 za2 = pk2(z0[k], z0[k]);
        u64 zb2 = pk2(z1p[k], z1p[k]);
        ulonglong2 wv = *(const ulonglong2*)&w2s[k * 32 + jg * 4];
        ffma2(accA[0], za2, wv.x); ffma2(accA[1], za2, wv.y);
        ffma2(accB[0], zb2, wv.x); ffma2(accB[1], zb2, wv.y);
    }
    float2 a01 = upk2(accA[0]), a23 = upk2(accA[1]);
    float2 b01 = upk2(accB[0]), b23 = upk2(accB[1]);
    float p0 = fmaxf(a01.x, 0.f) * w3s[jg * 4 + 0] + fmaxf(a01.y, 0.f) * w3s[jg * 4 + 1]
             + fmaxf(a23.x, 0.f) * w3s[jg * 4 + 2] + fmaxf(a23.y, 0.f) * w3s[jg * 4 + 3];
    float p1 = fmaxf(b01.x, 0.f) * w3s[jg * 4 + 0] + fmaxf(b01.y, 0.f) * w3s[jg * 4 + 1]
             + fmaxf(b23.x, 0.f) * w3s[jg * 4 + 2] + fmaxf(b23.y, 0.f) * w3s[jg * 4 + 3];
#pragma unroll
    for (int off = 4; off; off >>= 1) {
        p0 += __shfl_down_sync(0xffffffffu, p0, off, 8);
        p1 += __shfl_down_sync(0xffffffffu, p1, off, 8);
    }
    if (jg == 0) {
        float b3 = bp3[0];
        out[e0 + ebase]     = 1.f / (1.f + __expf(-(p0 + b3)));
        out[e0 + ebase + 1] = 1.f / (1.f + __expf(-(p1 + b3)));
    }
}

extern "C" void kernel_launch(void* const* d_in, const int* in_sizes, int n_in,
                              void* d_out, int out_size) {
    const float* x       = (const float*)d_in[0];
    const int*   raw_src = (const int*)d_in[1];
    const int*   raw_dst = (const int*)d_in[2];
    const float* W1  = (const float*)d_in[3];
    const float* b1  = (const float*)d_in[4];
    const float* W2  = (const float*)d_in[5];
    const float* b2  = (const float*)d_in[6];
    const float* Wp1 = (const float*)d_in[7];
    const float* bp1 = (const float*)d_in[8];
    const float* Wp2 = (const float*)d_in[9];
    const float* bp2 = (const float*)d_in[10];
    const float* Wp3 = (const float*)d_in[11];
    const float* bp3 = (const float*)d_in[12];
    float* out = (float*)d_out;

    float4 *bufA, *bufB;
    float *invOut, *invIn;
    cudaGetSymbolAddress((void**)&bufA, g_bufA);
    cudaGetSymbolAddress((void**)&bufB, g_bufB);
    cudaGetSymbolAddress((void**)&invOut, g_deg_out);
    cudaGetSymbolAddress((void**)&invIn, g_deg_in);

    const int NB_GEMM = (N_NODES + 63) / 64;   // 1563
    const int NB_E = (N_EDGES + 255) / 256;    // 6250
    const int NB_AGG = N_NODES / 8;            // 12500

    // decode + dst-CSR build (histogram, scan, placement) + degrees
    k_probe<<<1, 256>>>(raw_src, raw_dst);
    k_decode<<<NB_E, 256>>>(raw_src, raw_dst);
    k_init<<<SCAN_B, 256>>>();
    k_hist<<<NB_E, 256>>>();
    k_finalize_deg<<<SCAN_B, 256>>>();
    k_scan1<<<SCAN_B, 256>>>();
    k_scan2<<<1, 512>>>();
    k_scan3<<<SCAN_B, 256>>>();
    k_place<<<NB_E, 256>>>();

    // layer 1: h1pre = (x*rs_out) @ W1 ; agg1 = csr-sum(h1pre)
    k_gemm<128, 128, false, 0><<<NB_GEMM, 256>>>(x, W1, invOut, nullptr, nullptr, (float*)bufA);
    k_agg32<<<NB_AGG, 256>>>(bufA, bufB);

    // layer 2 (fused post): h2pre = (relu(agg1*rin + b1) * rs_out) @ W2 ; agg2 = csr-sum(h2pre)
    k_gemm<128, 64, false, 1><<<NB_GEMM, 256>>>((const float*)bufB, W2, invOut, invIn, b1,
                                                (float*)bufA);
    k_agg16<<<NB_AGG, 256>>>((const float2*)bufA, (float2*)(bufB + N_NODES * 16));

    // predictor (fused post): uv = (agg2*rin + b2) @ [Wp1_top | Wp1_bot]
    k_gemm<64, 128, true, 2><<<NB_GEMM, 256>>>((const float*)(bufB + N_NODES * 16), Wp1,
                                               nullptr, invIn, b2, (float*)bufA);

    // edge MLP
    k_edge<<<N_EDGES / 64, 256>>>(bufA, bp1, Wp2, bp2, Wp3, bp3, out);
}